// round 8
// baseline (speedup 1.0000x reference)
#include <cuda_runtime.h>
#include <cuda_fp16.h>
#include <cstdint>

#define B_DIM 1024
#define Z_DIM 32768
#define D_DIM 128

constexpr int NCHUNK = 18;    // 16 x 18 = 288 CTAs = one wave at 2 CTAs/SM
constexpr int NZT = 256;      // total 128-wide z tiles
constexpr int THREADS = 128;  // 4 warps, each owns a 16-row batch band (64-row CTA)
// 1/sqrt(128) * log2(e): softmax computed in base-2 (consistent num/denom)
constexpr float SCALE2 = 0.088388347648318447f * 1.4426950408889634f;

constexpr int MASK_P = 132;                    // byte pitch per row
constexpr int MASK_BUF = 64 * MASK_P;          // 8448 B per stage
// smem: 2-stage emb fp16 (2x32KB), ctx fp16 (16KB), 2-stage byte mask
constexpr int SM_EMB  = 0;
constexpr int SM_CTX  = 65536;
constexpr int SM_MASK = 81920;
constexpr int SM_TOTAL = SM_MASK + 2 * MASK_BUF;   // 98816 B -> 2 CTAs/SM

__device__ uint32_t g_emb16[Z_DIM * D_DIM / 2];      // fp16x2 table, 8 MB
__device__ float g_pacc[NCHUNK * B_DIM * D_DIM];     // 9.4 MB partials
__device__ float g_pss[NCHUNK * B_DIM];
__device__ int   g_pcnt[NCHUNK * B_DIM];

__device__ __forceinline__ uint32_t smem_u32(const void* p) {
    uint32_t a;
    asm("{ .reg .u64 t; cvta.to.shared.u64 t, %1; cvt.u32.u64 %0, t; }" : "=r"(a) : "l"(p));
    return a;
}
__device__ __forceinline__ uint32_t pk(float lo, float hi) {   // f16x2: lower=lo
    uint32_t r;
    asm("cvt.rn.f16x2.f32 %0, %1, %2;" : "=r"(r) : "f"(hi), "f"(lo));
    return r;
}
__device__ __forceinline__ float ex2f(float x) {
    float y;
    asm("ex2.approx.f32 %0, %1;" : "=f"(y) : "f"(x));
    return y;
}
__device__ __forceinline__ void ldsm4(uint32_t& r0, uint32_t& r1, uint32_t& r2, uint32_t& r3,
                                      uint32_t a) {
    asm volatile("ldmatrix.sync.aligned.m8n8.x4.shared.b16 {%0,%1,%2,%3}, [%4];"
                 : "=r"(r0), "=r"(r1), "=r"(r2), "=r"(r3) : "r"(a));
}
__device__ __forceinline__ void ldsm4t(uint32_t& r0, uint32_t& r1, uint32_t& r2, uint32_t& r3,
                                       uint32_t a) {
    asm volatile("ldmatrix.sync.aligned.m8n8.x4.trans.shared.b16 {%0,%1,%2,%3}, [%4];"
                 : "=r"(r0), "=r"(r1), "=r"(r2), "=r"(r3) : "r"(a));
}
__device__ __forceinline__ void mma16816(float* c, const uint32_t* a, uint32_t b0, uint32_t b1) {
    asm volatile("mma.sync.aligned.m16n8k16.row.col.f32.f16.f16.f32 "
                 "{%0,%1,%2,%3}, {%4,%5,%6,%7}, {%8,%9}, {%0,%1,%2,%3};"
                 : "+f"(c[0]), "+f"(c[1]), "+f"(c[2]), "+f"(c[3])
                 : "r"(a[0]), "r"(a[1]), "r"(a[2]), "r"(a[3]), "r"(b0), "r"(b1));
}
__device__ __forceinline__ void cp16(uint32_t dst, const void* src) {
    asm volatile("cp.async.cg.shared.global [%0], [%1], 16;" :: "r"(dst), "l"(src));
}

// fp32 table -> fp16 (linear layout), one uint4 per thread
__global__ void conv_emb(const float* __restrict__ emb) {
    int f = blockIdx.x * 256 + threadIdx.x;          // 524288 threads
    const float4* s = reinterpret_cast<const float4*>(emb) + (size_t)f * 2;
    float4 v0 = s[0], v1 = s[1];
    uint4 o;
    o.x = pk(v0.x, v0.y); o.y = pk(v0.z, v0.w);
    o.z = pk(v1.x, v1.y); o.w = pk(v1.z, v1.w);
    reinterpret_cast<uint4*>(g_emb16)[f] = o;
}

__global__ __launch_bounds__(THREADS, 2) void stage2_mma(
    const int* __restrict__ zs, const float* __restrict__ ctx)
{
    extern __shared__ __align__(128) char smem[];
    const uint32_t sb = smem_u32(smem);
    const int tid = threadIdx.x, w = tid >> 5, lane = tid & 31;
    const int b0 = blockIdx.x * 64;                  // 64-row batch tile
    const int chunk = blockIdx.y;
    const int t0 = chunk * NZT / NCHUNK;
    const int t1 = (chunk + 1) * NZT / NCHUNK;
    const int wrow0 = w * 16;                        // w < 4
    const int sub = lane >> 3, l7 = lane & 7;
    const int g = lane >> 2, tq = lane & 3;
    const char* embg = reinterpret_cast<const char*>(g_emb16);

    // ---- prologue: emb(t0) -> ebuf0 (async), mask(t0) -> mbuf0, ctx staged
#pragma unroll
    for (int it = 0; it < 16; it++) {
        int f = it * THREADS + tid, r = f >> 4, c = f & 15;
        cp16(sb + SM_EMB + r * 256 + ((c ^ (r & 7)) << 4),
             embg + ((size_t)t0 * 128 + r) * 256 + c * 16);
    }
    asm volatile("cp.async.commit_group;" ::: "memory");
#pragma unroll
    for (int it = 0; it < 16; it++) {
        int row = it * 4 + w;
        int4 m = *reinterpret_cast<const int4*>(
            &zs[(size_t)(b0 + row) * Z_DIM + t0 * 128 + lane * 4]);
        uchar4 mb;
        mb.x = (m.x > 0); mb.y = (m.y > 0); mb.z = (m.z > 0); mb.w = (m.w > 0);
        *reinterpret_cast<uchar4*>(smem + SM_MASK + row * MASK_P + lane * 4) = mb;
    }
    // ctx (scaled by 1/sqrt(128)*log2e) -> fp16 swizzled, 64 rows
#pragma unroll
    for (int it = 0; it < 8; it++) {
        int f = it * THREADS + tid, r = f >> 4, c = f & 15;
        const float4* s = reinterpret_cast<const float4*>(&ctx[(size_t)(b0 + r) * D_DIM + c * 8]);
        float4 v0 = s[0], v1 = s[1];
        uint4 o;
        o.x = pk(v0.x * SCALE2, v0.y * SCALE2); o.y = pk(v0.z * SCALE2, v0.w * SCALE2);
        o.z = pk(v1.x * SCALE2, v1.y * SCALE2); o.w = pk(v1.z * SCALE2, v1.w * SCALE2);
        *reinterpret_cast<uint4*>(smem + SM_CTX + r * 256 + ((c ^ (r & 7)) << 4)) = o;
    }
    __syncthreads();

    // persistent A fragments of ctx (8 k-steps x 4 regs)
    uint32_t aCtx[8][4];
#pragma unroll
    for (int kk = 0; kk < 8; kk++) {
        int rm = wrow0 + ((sub & 1) << 3) + l7;
        int ch = 2 * kk + (sub >> 1);
        ldsm4(aCtx[kk][0], aCtx[kk][1], aCtx[kk][2], aCtx[kk][3],
              sb + SM_CTX + rm * 256 + ((ch ^ (rm & 7)) << 4));
    }

    float o[16][4];
#pragma unroll
    for (int i = 0; i < 16; i++)
#pragma unroll
        for (int j = 0; j < 4; j++) o[i][j] = 0.f;
    float ssum0 = 0.f, ssum1 = 0.f;
    int cnt0 = 0, cnt1 = 0;

    for (int t = t0; t < t1; t++) {
        const int cur = (t - t0) & 1;
        // ---- prefetch tile t+1 into the other stage (safe: B2 of previous iter)
        if (t + 1 < t1) {
#pragma unroll
            for (int it = 0; it < 16; it++) {
                int f = it * THREADS + tid, r = f >> 4, c = f & 15;
                cp16(sb + SM_EMB + (1 - cur) * 32768 + r * 256 + ((c ^ (r & 7)) << 4),
                     embg + ((size_t)(t + 1) * 128 + r) * 256 + c * 16);
            }
        }
        asm volatile("cp.async.commit_group;" ::: "memory");
        if (t + 1 < t1) {
#pragma unroll
            for (int it = 0; it < 16; it++) {
                int row = it * 4 + w;
                int4 m = *reinterpret_cast<const int4*>(
                    &zs[(size_t)(b0 + row) * Z_DIM + (t + 1) * 128 + lane * 4]);
                uchar4 mb;
                mb.x = (m.x > 0); mb.y = (m.y > 0); mb.z = (m.z > 0); mb.w = (m.w > 0);
                *reinterpret_cast<uchar4*>(
                    smem + SM_MASK + (1 - cur) * MASK_BUF + row * MASK_P + lane * 4) = mb;
            }
        }

        asm volatile("cp.async.wait_group 1;" ::: "memory");
        __syncthreads();   // B1: emb(t) + mask(t) visible to all warps

        const uint32_t eb = sb + SM_EMB + cur * 32768;
        const unsigned char* mask_s =
            reinterpret_cast<const unsigned char*>(smem + SM_MASK + cur * MASK_BUF);

        // S = ctx @ emb^T  (16 n8-frags over z)
        float s[16][4];
#pragma unroll
        for (int i = 0; i < 16; i++)
#pragma unroll
            for (int j = 0; j < 4; j++) s[i][j] = 0.f;
#pragma unroll
        for (int kk = 0; kk < 8; kk++) {
#pragma unroll
            for (int G = 0; G < 8; G++) {
                int rz = G * 16 + ((sub >> 1) << 3) + l7;
                int ch = 2 * kk + (sub & 1);
                uint32_t r0, r1, r2, r3;
                ldsm4(r0, r1, r2, r3, eb + rz * 256 + ((ch ^ (rz & 7)) << 4));
                mma16816(s[2 * G], aCtx[kk], r0, r1);
                mma16816(s[2 * G + 1], aCtx[kk], r2, r3);
            }
        }

        // softmax weights (base-2) in-register; S element (f, c):
        // row = wrow0+g (+8 for c2/c3), z = 8*f + 2*tq + {0,1}
        const unsigned char* mrow0 = &mask_s[(wrow0 + g) * MASK_P];
        const unsigned char* mrow1 = mrow0 + 8 * MASK_P;
#pragma unroll
        for (int f = 0; f < 16; f++) {
            int zb = 8 * f + 2 * tq;
            uchar2 a0 = *reinterpret_cast<const uchar2*>(&mrow0[zb]);
            uchar2 a1 = *reinterpret_cast<const uchar2*>(&mrow1[zb]);
            cnt0 += a0.x + a0.y;
            cnt1 += a1.x + a1.y;
            float v;
            v = a0.x ? ex2f(s[f][0]) : 0.f; s[f][0] = v; ssum0 += v;
            v = a0.y ? ex2f(s[f][1]) : 0.f; s[f][1] = v; ssum0 += v;
            v = a1.x ? ex2f(s[f][2]) : 0.f; s[f][2] = v; ssum1 += v;
            v = a1.y ? ex2f(s[f][3]) : 0.f; s[f][3] = v; ssum1 += v;
        }

        // O += W @ emb  (A = W from S-accums, B = trans ldmatrix of emb)
#pragma unroll
        for (int kk = 0; kk < 8; kk++) {
            uint32_t aW[4];
            aW[0] = pk(s[2 * kk][0], s[2 * kk][1]);
            aW[1] = pk(s[2 * kk][2], s[2 * kk][3]);
            aW[2] = pk(s[2 * kk + 1][0], s[2 * kk + 1][1]);
            aW[3] = pk(s[2 * kk + 1][2], s[2 * kk + 1][3]);
#pragma unroll
            for (int G = 0; G < 8; G++) {
                int rz = kk * 16 + ((sub & 1) << 3) + l7;
                int ch = 2 * G + (sub >> 1);
                uint32_t r0, r1, r2, r3;
                ldsm4t(r0, r1, r2, r3, eb + rz * 256 + ((ch ^ (rz & 7)) << 4));
                mma16816(o[2 * G], aW, r0, r1);
                mma16816(o[2 * G + 1], aW, r2, r3);
            }
        }
        __syncthreads();   // B2: stage buffers free for next prefetch
    }

    // reduce ssums/cnts across the 4 lanes of each row-group
    ssum0 += __shfl_xor_sync(0xffffffffu, ssum0, 1);
    ssum0 += __shfl_xor_sync(0xffffffffu, ssum0, 2);
    ssum1 += __shfl_xor_sync(0xffffffffu, ssum1, 1);
    ssum1 += __shfl_xor_sync(0xffffffffu, ssum1, 2);
    cnt0 += __shfl_xor_sync(0xffffffffu, cnt0, 1);
    cnt0 += __shfl_xor_sync(0xffffffffu, cnt0, 2);
    cnt1 += __shfl_xor_sync(0xffffffffu, cnt1, 1);
    cnt1 += __shfl_xor_sync(0xffffffffu, cnt1, 2);
    int r0i = wrow0 + g;
    if (tq == 0) {
        int idx = chunk * B_DIM + b0 + r0i;
        g_pss[idx] = ssum0;  g_pcnt[idx] = cnt0;
        g_pss[idx + 8] = ssum1; g_pcnt[idx + 8] = cnt1;
    }

    // write O partials: thread's (f, c) element is at column d = 8*f + 2*tq + c
    float* p0 = g_pacc + ((size_t)chunk * B_DIM + b0 + r0i) * D_DIM;
    float* p1 = p0 + 8 * D_DIM;
    const int t2 = tq * 2;
#pragma unroll
    for (int f = 0; f < 16; f++) {
        *reinterpret_cast<float2*>(&p0[f * 8 + t2]) = make_float2(o[f][0], o[f][1]);
        *reinterpret_cast<float2*>(&p1[f * 8 + t2]) = make_float2(o[f][2], o[f][3]);
    }
}

__global__ void stage2_finalize(float* __restrict__ out)
{
    int i = blockIdx.x * blockDim.x + threadIdx.x;
    if (i >= B_DIM * D_DIM) return;
    int b = i >> 7;
    float accv = 0.f, ss = 0.f;
    int cc = 0;
#pragma unroll
    for (int c = 0; c < NCHUNK; c++) {
        accv += g_pacc[(size_t)c * (B_DIM * D_DIM) + i];
        ss   += g_pss[c * B_DIM + b];
        cc   += g_pcnt[c * B_DIM + b];
    }
    out[i] = (ss > 0.f) ? accv / (ss * (float)cc) : 0.f;
}

extern "C" void kernel_launch(void* const* d_in, const int* in_sizes, int n_in,
                              void* d_out, int out_size)
{
    const int*   zs  = (const int*)d_in[0];
    const float* ctx = (const float*)d_in[1];
    const float* emb = (const float*)d_in[2];
    float* out = (float*)d_out;

    conv_emb<<<2048, 256>>>(emb);
    cudaFuncSetAttribute(stage2_mma, cudaFuncAttributeMaxDynamicSharedMemorySize, SM_TOTAL);
    stage2_mma<<<dim3(16, NCHUNK), THREADS, SM_TOTAL>>>(zs, ctx);
    stage2_finalize<<<(B_DIM * D_DIM + 255) / 256, 256>>>(out);
}

// round 9
// speedup vs baseline: 1.3392x; 1.3392x over previous
#include <cuda_runtime.h>
#include <cuda_fp16.h>
#include <cstdint>

#define B_DIM 1024
#define Z_DIM 32768
#define D_DIM 128

constexpr int NCHUNK = 18;    // 8 x 18 = 144 CTAs = one wave at 1 CTA/SM
constexpr int NZT = 256;      // total 128-wide z tiles
constexpr int THREADS = 256;  // 8 warps, each owns a 16-row batch band
// 1/sqrt(128) * log2(e): softmax computed in base-2 (consistent num/denom)
constexpr float SCALE2 = 0.088388347648318447f * 1.4426950408889634f;

constexpr int MASK_P = 132;   // byte pitch per row
constexpr int MASK_BUF = 128 * MASK_P;          // 16896 B per stage
// smem: 3-stage emb fp16, ctx fp16, 3-stage byte mask
constexpr int SM_EMB  = 0;                      // 3 x 32768
constexpr int SM_CTX  = 98304;                  // 32768
constexpr int SM_MASK = 131072;                 // 3 x 16896
constexpr int SM_TOTAL = SM_MASK + 3 * MASK_BUF;   // 181760

__device__ uint32_t g_emb16[Z_DIM * D_DIM / 2];      // fp16x2 table, 8 MB
__device__ float g_pacc[NCHUNK * B_DIM * D_DIM];     // 9.4 MB partials
__device__ float g_pss[NCHUNK * B_DIM];
__device__ int   g_pcnt[NCHUNK * B_DIM];

__device__ __forceinline__ uint32_t smem_u32(const void* p) {
    uint32_t a;
    asm("{ .reg .u64 t; cvta.to.shared.u64 t, %1; cvt.u32.u64 %0, t; }" : "=r"(a) : "l"(p));
    return a;
}
__device__ __forceinline__ uint32_t pk(float lo, float hi) {   // f16x2: lower=lo
    uint32_t r;
    asm("cvt.rn.f16x2.f32 %0, %1, %2;" : "=r"(r) : "f"(hi), "f"(lo));
    return r;
}
__device__ __forceinline__ uint32_t ex2h2(uint32_t x) {        // packed fp16 2^x
    uint32_t y;
    asm("ex2.approx.f16x2 %0, %1;" : "=r"(y) : "r"(x));
    return y;
}
__device__ __forceinline__ uint32_t hadd2(uint32_t a, uint32_t b) {
    uint32_t y;
    asm("add.rn.f16x2 %0, %1, %2;" : "=r"(y) : "r"(a), "r"(b));
    return y;
}
__device__ __forceinline__ uint32_t prmt_sign(uint32_t m) {    // bytes 0xFF/0x00 -> half-lane mask
    uint32_t y;
    asm("prmt.b32 %0, %1, 0, 0x9988;" : "=r"(y) : "r"(m));
    return y;
}
__device__ __forceinline__ void ldsm4(uint32_t& r0, uint32_t& r1, uint32_t& r2, uint32_t& r3,
                                      uint32_t a) {
    asm volatile("ldmatrix.sync.aligned.m8n8.x4.shared.b16 {%0,%1,%2,%3}, [%4];"
                 : "=r"(r0), "=r"(r1), "=r"(r2), "=r"(r3) : "r"(a));
}
__device__ __forceinline__ void ldsm4t(uint32_t& r0, uint32_t& r1, uint32_t& r2, uint32_t& r3,
                                       uint32_t a) {
    asm volatile("ldmatrix.sync.aligned.m8n8.x4.trans.shared.b16 {%0,%1,%2,%3}, [%4];"
                 : "=r"(r0), "=r"(r1), "=r"(r2), "=r"(r3) : "r"(a));
}
__device__ __forceinline__ void mma16816(float* c, const uint32_t* a, uint32_t b0, uint32_t b1) {
    asm volatile("mma.sync.aligned.m16n8k16.row.col.f32.f16.f16.f32 "
                 "{%0,%1,%2,%3}, {%4,%5,%6,%7}, {%8,%9}, {%0,%1,%2,%3};"
                 : "+f"(c[0]), "+f"(c[1]), "+f"(c[2]), "+f"(c[3])
                 : "r"(a[0]), "r"(a[1]), "r"(a[2]), "r"(a[3]), "r"(b0), "r"(b1));
}
__device__ __forceinline__ void cp16(uint32_t dst, const void* src) {
    asm volatile("cp.async.cg.shared.global [%0], [%1], 16;" :: "r"(dst), "l"(src));
}

// fp32 table -> fp16 (linear layout), one uint4 per thread
__global__ void conv_emb(const float* __restrict__ emb) {
    int f = blockIdx.x * 256 + threadIdx.x;          // 524288 threads
    const float4* s = reinterpret_cast<const float4*>(emb) + (size_t)f * 2;
    float4 v0 = s[0], v1 = s[1];
    uint4 o;
    o.x = pk(v0.x, v0.y); o.y = pk(v0.z, v0.w);
    o.z = pk(v1.x, v1.y); o.w = pk(v1.z, v1.w);
    reinterpret_cast<uint4*>(g_emb16)[f] = o;
}

__global__ __launch_bounds__(THREADS, 1) void stage2_mma(
    const int* __restrict__ zs, const float* __restrict__ ctx)
{
    extern __shared__ __align__(128) char smem[];
    const uint32_t sb = smem_u32(smem);
    const int tid = threadIdx.x, w = tid >> 5, lane = tid & 31;
    const int b0 = blockIdx.x * 128;
    const int chunk = blockIdx.y;
    const int t0 = chunk * NZT / NCHUNK;
    const int t1 = (chunk + 1) * NZT / NCHUNK;
    const int wrow0 = w * 16;
    const int sub = lane >> 3, l7 = lane & 7;
    const int g = lane >> 2, tq = lane & 3;
    const char* embg = reinterpret_cast<const char*>(g_emb16);

    // ---- prologue: stage tile t0 (emb via cp.async into buf0, mask into buf0)
#pragma unroll
    for (int it = 0; it < 8; it++) {
        int f = it * THREADS + tid, r = f >> 4, c = f & 15;
        cp16(sb + SM_EMB + r * 256 + ((c ^ (r & 7)) << 4),
             embg + ((size_t)t0 * 128 + r) * 256 + c * 16);
    }
    asm volatile("cp.async.commit_group;" ::: "memory");
#pragma unroll
    for (int it = 0; it < 16; it++) {
        int row = it * 8 + w;
        int4 m = *reinterpret_cast<const int4*>(
            &zs[(size_t)(b0 + row) * Z_DIM + t0 * 128 + lane * 4]);
        uchar4 mb;
        mb.x = (m.x > 0) ? 0xFFu : 0u; mb.y = (m.y > 0) ? 0xFFu : 0u;
        mb.z = (m.z > 0) ? 0xFFu : 0u; mb.w = (m.w > 0) ? 0xFFu : 0u;
        *reinterpret_cast<uchar4*>(smem + SM_MASK + row * MASK_P + lane * 4) = mb;
    }

    // stage ctx (scaled by 1/sqrt(128)*log2e) -> fp16 swizzled
#pragma unroll
    for (int it = 0; it < 8; it++) {
        int f = it * THREADS + tid, r = f >> 4, c = f & 15;
        const float4* s = reinterpret_cast<const float4*>(&ctx[(size_t)(b0 + r) * D_DIM + c * 8]);
        float4 v0 = s[0], v1 = s[1];
        uint4 o;
        o.x = pk(v0.x * SCALE2, v0.y * SCALE2); o.y = pk(v0.z * SCALE2, v0.w * SCALE2);
        o.z = pk(v1.x * SCALE2, v1.y * SCALE2); o.w = pk(v1.z * SCALE2, v1.w * SCALE2);
        *reinterpret_cast<uint4*>(smem + SM_CTX + r * 256 + ((c ^ (r & 7)) << 4)) = o;
    }
    __syncthreads();

    // persistent A fragments of ctx (8 k-steps x 4 regs)
    uint32_t aCtx[8][4];
#pragma unroll
    for (int kk = 0; kk < 8; kk++) {
        int rm = wrow0 + ((sub & 1) << 3) + l7;
        int ch = 2 * kk + (sub >> 1);
        ldsm4(aCtx[kk][0], aCtx[kk][1], aCtx[kk][2], aCtx[kk][3],
              sb + SM_CTX + rm * 256 + ((ch ^ (rm & 7)) << 4));
    }

    float o[16][4];
#pragma unroll
    for (int i = 0; i < 16; i++)
#pragma unroll
        for (int j = 0; j < 4; j++) o[i][j] = 0.f;
    float ssum0 = 0.f, ssum1 = 0.f;
    int cnt0 = 0, cnt1 = 0;
    int cur = 0;  // rotating stage index for tile t

    for (int t = t0; t < t1; t++) {
        const int nxt = (cur == 2) ? 0 : cur + 1;
        // ---- prefetch tile t+1 into stage `nxt` (emb async, mask LDG->STS)
        if (t + 1 < t1) {
#pragma unroll
            for (int it = 0; it < 8; it++) {
                int f = it * THREADS + tid, r = f >> 4, c = f & 15;
                cp16(sb + SM_EMB + nxt * 32768 + r * 256 + ((c ^ (r & 7)) << 4),
                     embg + ((size_t)(t + 1) * 128 + r) * 256 + c * 16);
            }
        }
        asm volatile("cp.async.commit_group;" ::: "memory");
        if (t + 1 < t1) {
#pragma unroll
            for (int it = 0; it < 16; it++) {
                int row = it * 8 + w;
                int4 m = *reinterpret_cast<const int4*>(
                    &zs[(size_t)(b0 + row) * Z_DIM + (t + 1) * 128 + lane * 4]);
                uchar4 mb;
                mb.x = (m.x > 0) ? 0xFFu : 0u; mb.y = (m.y > 0) ? 0xFFu : 0u;
                mb.z = (m.z > 0) ? 0xFFu : 0u; mb.w = (m.w > 0) ? 0xFFu : 0u;
                *reinterpret_cast<uchar4*>(
                    smem + SM_MASK + nxt * MASK_BUF + row * MASK_P + lane * 4) = mb;
            }
        }

        asm volatile("cp.async.wait_group 1;" ::: "memory");
        __syncthreads();   // single barrier per tile: emb[t] + mask[t] ready everywhere

        const uint32_t eb = sb + SM_EMB + cur * 32768;
        const unsigned char* mask_s =
            reinterpret_cast<const unsigned char*>(smem + SM_MASK + cur * MASK_BUF);

        // S = ctx @ emb^T  (16 n8-frags over z)
        float s[16][4];
#pragma unroll
        for (int i = 0; i < 16; i++)
#pragma unroll
            for (int j = 0; j < 4; j++) s[i][j] = 0.f;
#pragma unroll
        for (int kk = 0; kk < 8; kk++) {
#pragma unroll
            for (int G = 0; G < 8; G++) {
                int rz = G * 16 + ((sub >> 1) << 3) + l7;
                int ch = 2 * kk + (sub & 1);
                uint32_t r0, r1, r2, r3;
                ldsm4(r0, r1, r2, r3, eb + rz * 256 + ((ch ^ (rz & 7)) << 4));
                mma16816(s[2 * G], aCtx[kk], r0, r1);
                mma16816(s[2 * G + 1], aCtx[kk], r2, r3);
            }
        }

        // packed-f16 softmax weights: W = ex2(score_h2) & lane-mask.
        // S element (f,c): row = wrow0+g (c0/c1) or +8 (c2/c3); z = 8*f + 2*tq + {0,1}
        const unsigned char* mrow0 = &mask_s[(wrow0 + g) * MASK_P];
        const unsigned char* mrow1 = mrow0 + 8 * MASK_P;
        uint32_t wlo[16], whi[16];
        uint32_t sa0 = 0, sa1 = 0;   // per-tile half2 accumulators
#pragma unroll
        for (int f = 0; f < 16; f++) {
            int zb = 8 * f + 2 * tq;
            uint32_t m0 = *reinterpret_cast<const unsigned short*>(&mrow0[zb]);
            uint32_t m1 = *reinterpret_cast<const unsigned short*>(&mrow1[zb]);
            cnt0 += __popc(m0);          // 8 per active feature
            cnt1 += __popc(m1);
            uint32_t w0 = ex2h2(pk(s[f][0], s[f][1])) & prmt_sign(m0);
            uint32_t w1 = ex2h2(pk(s[f][2], s[f][3])) & prmt_sign(m1);
            wlo[f] = w0; whi[f] = w1;
            sa0 = hadd2(sa0, w0);
            sa1 = hadd2(sa1, w1);
        }
        {   // fold per-tile half2 sums into fp32 running sums
            __half2 h0 = *reinterpret_cast<__half2*>(&sa0);
            __half2 h1 = *reinterpret_cast<__half2*>(&sa1);
            ssum0 += __low2float(h0) + __high2float(h0);
            ssum1 += __low2float(h1) + __high2float(h1);
        }

        // O += W @ emb  (A = packed W, B = trans ldmatrix of emb)
#pragma unroll
        for (int kk = 0; kk < 8; kk++) {
            uint32_t aW[4] = { wlo[2 * kk], whi[2 * kk], wlo[2 * kk + 1], whi[2 * kk + 1] };
#pragma unroll
            for (int G = 0; G < 8; G++) {
                int rz = kk * 16 + ((sub & 1) << 3) + l7;
                int ch = 2 * G + (sub >> 1);
                uint32_t r0, r1, r2, r3;
                ldsm4t(r0, r1, r2, r3, eb + rz * 256 + ((ch ^ (rz & 7)) << 4));
                mma16816(o[2 * G], aW, r0, r1);
                mma16816(o[2 * G + 1], aW, r2, r3);
            }
        }
        cur = nxt;
    }

    // reduce ssums/cnts across the 4 lanes of each row-group
    ssum0 += __shfl_xor_sync(0xffffffffu, ssum0, 1);
    ssum0 += __shfl_xor_sync(0xffffffffu, ssum0, 2);
    ssum1 += __shfl_xor_sync(0xffffffffu, ssum1, 1);
    ssum1 += __shfl_xor_sync(0xffffffffu, ssum1, 2);
    cnt0 += __shfl_xor_sync(0xffffffffu, cnt0, 1);
    cnt0 += __shfl_xor_sync(0xffffffffu, cnt0, 2);
    cnt1 += __shfl_xor_sync(0xffffffffu, cnt1, 1);
    cnt1 += __shfl_xor_sync(0xffffffffu, cnt1, 2);
    int r0i = wrow0 + g;
    if (tq == 0) {
        int idx = chunk * B_DIM + b0 + r0i;
        g_pss[idx] = ssum0;  g_pcnt[idx] = cnt0 >> 3;
        g_pss[idx + 8] = ssum1; g_pcnt[idx + 8] = cnt1 >> 3;
    }

    // write O partials: thread's (f, c) element is at column d = 8*f + 2*tq + c
    float* p0 = g_pacc + ((size_t)chunk * B_DIM + b0 + r0i) * D_DIM;
    float* p1 = p0 + 8 * D_DIM;
    const int t2 = tq * 2;
#pragma unroll
    for (int f = 0; f < 16; f++) {
        *reinterpret_cast<float2*>(&p0[f * 8 + t2]) = make_float2(o[f][0], o[f][1]);
        *reinterpret_cast<float2*>(&p1[f * 8 + t2]) = make_float2(o[f][2], o[f][3]);
    }
}

__global__ void stage2_finalize(float* __restrict__ out)
{
    int i = blockIdx.x * blockDim.x + threadIdx.x;
    if (i >= B_DIM * D_DIM) return;
    int b = i >> 7;
    float accv = 0.f, ss = 0.f;
    int cc = 0;
#pragma unroll
    for (int c = 0; c < NCHUNK; c++) {
        accv += g_pacc[(size_t)c * (B_DIM * D_DIM) + i];
        ss   += g_pss[c * B_DIM + b];
        cc   += g_pcnt[c * B_DIM + b];
    }
    out[i] = (ss > 0.f) ? accv / (ss * (float)cc) : 0.f;
}

extern "C" void kernel_launch(void* const* d_in, const int* in_sizes, int n_in,
                              void* d_out, int out_size)
{
    const int*   zs  = (const int*)d_in[0];
    const float* ctx = (const float*)d_in[1];
    const float* emb = (const float*)d_in[2];
    float* out = (float*)d_out;

    conv_emb<<<2048, 256>>>(emb);
    cudaFuncSetAttribute(stage2_mma, cudaFuncAttributeMaxDynamicSharedMemorySize, SM_TOTAL);
    stage2_mma<<<dim3(8, NCHUNK), THREADS, SM_TOTAL>>>(zs, ctx);
    stage2_finalize<<<(B_DIM * D_DIM + 255) / 256, 256>>>(out);
}

// round 10
// speedup vs baseline: 1.3640x; 1.0186x over previous
#include <cuda_runtime.h>
#include <cuda_fp16.h>
#include <cstdint>

#define B_DIM 1024
#define Z_DIM 32768
#define D_DIM 128

constexpr int NCHUNK = 18;    // 8 x 18 = 144 CTAs = one wave at 1 CTA/SM
constexpr int NZT = 256;      // total 128-wide z tiles
constexpr int THREADS = 256;  // 8 warps, each owns a 16-row batch band
// 1/sqrt(128) * log2(e): softmax computed in base-2 (consistent num/denom)
constexpr float SCALE2 = 0.088388347648318447f * 1.4426950408889634f;

constexpr int MASK_P = 132;   // byte pitch per row
constexpr int MASK_BUF = 128 * MASK_P;          // 16896 B per stage
// smem: 3-stage emb fp16, ctx fp16, 3-stage byte mask
constexpr int SM_EMB  = 0;                      // 3 x 32768
constexpr int SM_CTX  = 98304;                  // 32768
constexpr int SM_MASK = 131072;                 // 3 x 16896
constexpr int SM_TOTAL = SM_MASK + 3 * MASK_BUF;   // 181760

__device__ uint32_t g_emb16[Z_DIM * D_DIM / 2];      // fp16x2 table, 8 MB
__device__ float g_pacc[NCHUNK * B_DIM * D_DIM];     // 9.4 MB partials
__device__ float g_pss[NCHUNK * B_DIM];
__device__ int   g_pcnt[NCHUNK * B_DIM];

__device__ __forceinline__ uint32_t smem_u32(const void* p) {
    uint32_t a;
    asm("{ .reg .u64 t; cvta.to.shared.u64 t, %1; cvt.u32.u64 %0, t; }" : "=r"(a) : "l"(p));
    return a;
}
__device__ __forceinline__ uint32_t pk(float lo, float hi) {   // f16x2: lower=lo
    uint32_t r;
    asm("cvt.rn.f16x2.f32 %0, %1, %2;" : "=r"(r) : "f"(hi), "f"(lo));
    return r;
}
__device__ __forceinline__ uint32_t ex2h2(uint32_t x) {        // packed fp16 2^x
    uint32_t y;
    asm("ex2.approx.f16x2 %0, %1;" : "=r"(y) : "r"(x));
    return y;
}
__device__ __forceinline__ uint32_t hadd2(uint32_t a, uint32_t b) {
    uint32_t y;
    asm("add.rn.f16x2 %0, %1, %2;" : "=r"(y) : "r"(a), "r"(b));
    return y;
}
__device__ __forceinline__ uint32_t prmt_sign(uint32_t m) {    // bytes 0xFF/0x00 -> half-lane mask
    uint32_t y;
    asm("prmt.b32 %0, %1, 0, 0x9988;" : "=r"(y) : "r"(m));
    return y;
}
__device__ __forceinline__ void ldsm4(uint32_t& r0, uint32_t& r1, uint32_t& r2, uint32_t& r3,
                                      uint32_t a) {
    asm volatile("ldmatrix.sync.aligned.m8n8.x4.shared.b16 {%0,%1,%2,%3}, [%4];"
                 : "=r"(r0), "=r"(r1), "=r"(r2), "=r"(r3) : "r"(a));
}
__device__ __forceinline__ void ldsm4t(uint32_t& r0, uint32_t& r1, uint32_t& r2, uint32_t& r3,
                                       uint32_t a) {
    asm volatile("ldmatrix.sync.aligned.m8n8.x4.trans.shared.b16 {%0,%1,%2,%3}, [%4];"
                 : "=r"(r0), "=r"(r1), "=r"(r2), "=r"(r3) : "r"(a));
}
// fp32-accumulate HMMA (PV GEMM)
__device__ __forceinline__ void mma16816(float* c, const uint32_t* a, uint32_t b0, uint32_t b1) {
    asm volatile("mma.sync.aligned.m16n8k16.row.col.f32.f16.f16.f32 "
                 "{%0,%1,%2,%3}, {%4,%5,%6,%7}, {%8,%9}, {%0,%1,%2,%3};"
                 : "+f"(c[0]), "+f"(c[1]), "+f"(c[2]), "+f"(c[3])
                 : "r"(a[0]), "r"(a[1]), "r"(a[2]), "r"(a[3]), "r"(b0), "r"(b1));
}
// fp16-accumulate HMMA (S GEMM, 2x rate; C packed half2, same layout as PV's A operand)
__device__ __forceinline__ void mma16816h(uint32_t* c, const uint32_t* a, uint32_t b0, uint32_t b1) {
    asm volatile("mma.sync.aligned.m16n8k16.row.col.f16.f16.f16.f16 "
                 "{%0,%1}, {%2,%3,%4,%5}, {%6,%7}, {%0,%1};"
                 : "+r"(c[0]), "+r"(c[1])
                 : "r"(a[0]), "r"(a[1]), "r"(a[2]), "r"(a[3]), "r"(b0), "r"(b1));
}
__device__ __forceinline__ void cp16(uint32_t dst, const void* src) {
    asm volatile("cp.async.cg.shared.global [%0], [%1], 16;" :: "r"(dst), "l"(src));
}

// fp32 table -> fp16 (linear layout), one uint4 per thread
__global__ void conv_emb(const float* __restrict__ emb) {
    int f = blockIdx.x * 256 + threadIdx.x;          // 524288 threads
    const float4* s = reinterpret_cast<const float4*>(emb) + (size_t)f * 2;
    float4 v0 = s[0], v1 = s[1];
    uint4 o;
    o.x = pk(v0.x, v0.y); o.y = pk(v0.z, v0.w);
    o.z = pk(v1.x, v1.y); o.w = pk(v1.z, v1.w);
    reinterpret_cast<uint4*>(g_emb16)[f] = o;
}

__global__ __launch_bounds__(THREADS, 1) void stage2_mma(
    const int* __restrict__ zs, const float* __restrict__ ctx)
{
    extern __shared__ __align__(128) char smem[];
    const uint32_t sb = smem_u32(smem);
    const int tid = threadIdx.x, w = tid >> 5, lane = tid & 31;
    const int b0 = blockIdx.x * 128;
    const int chunk = blockIdx.y;
    const int t0 = chunk * NZT / NCHUNK;
    const int t1 = (chunk + 1) * NZT / NCHUNK;
    const int wrow0 = w * 16;
    const int sub = lane >> 3, l7 = lane & 7;
    const int g = lane >> 2, tq = lane & 3;
    const char* embg = reinterpret_cast<const char*>(g_emb16);

    // ---- prologue: stage tile t0 (emb via cp.async into buf0, mask into buf0)
#pragma unroll
    for (int it = 0; it < 8; it++) {
        int f = it * THREADS + tid, r = f >> 4, c = f & 15;
        cp16(sb + SM_EMB + r * 256 + ((c ^ (r & 7)) << 4),
             embg + ((size_t)t0 * 128 + r) * 256 + c * 16);
    }
    asm volatile("cp.async.commit_group;" ::: "memory");
#pragma unroll
    for (int it = 0; it < 16; it++) {
        int row = it * 8 + w;
        int4 m = *reinterpret_cast<const int4*>(
            &zs[(size_t)(b0 + row) * Z_DIM + t0 * 128 + lane * 4]);
        uchar4 mb;
        mb.x = (m.x > 0) ? 0xFFu : 0u; mb.y = (m.y > 0) ? 0xFFu : 0u;
        mb.z = (m.z > 0) ? 0xFFu : 0u; mb.w = (m.w > 0) ? 0xFFu : 0u;
        *reinterpret_cast<uchar4*>(smem + SM_MASK + row * MASK_P + lane * 4) = mb;
    }

    // stage ctx (scaled by 1/sqrt(128)*log2e) -> fp16 swizzled
#pragma unroll
    for (int it = 0; it < 8; it++) {
        int f = it * THREADS + tid, r = f >> 4, c = f & 15;
        const float4* s = reinterpret_cast<const float4*>(&ctx[(size_t)(b0 + r) * D_DIM + c * 8]);
        float4 v0 = s[0], v1 = s[1];
        uint4 o;
        o.x = pk(v0.x * SCALE2, v0.y * SCALE2); o.y = pk(v0.z * SCALE2, v0.w * SCALE2);
        o.z = pk(v1.x * SCALE2, v1.y * SCALE2); o.w = pk(v1.z * SCALE2, v1.w * SCALE2);
        *reinterpret_cast<uint4*>(smem + SM_CTX + r * 256 + ((c ^ (r & 7)) << 4)) = o;
    }
    __syncthreads();

    // persistent A fragments of ctx (8 k-steps x 4 regs)
    uint32_t aCtx[8][4];
#pragma unroll
    for (int kk = 0; kk < 8; kk++) {
        int rm = wrow0 + ((sub & 1) << 3) + l7;
        int ch = 2 * kk + (sub >> 1);
        ldsm4(aCtx[kk][0], aCtx[kk][1], aCtx[kk][2], aCtx[kk][3],
              sb + SM_CTX + rm * 256 + ((ch ^ (rm & 7)) << 4));
    }

    float o[16][4];
#pragma unroll
    for (int i = 0; i < 16; i++)
#pragma unroll
        for (int j = 0; j < 4; j++) o[i][j] = 0.f;
    float ssum0 = 0.f, ssum1 = 0.f;
    int cnt0 = 0, cnt1 = 0;
    int cur = 0;  // rotating stage index for tile t

    for (int t = t0; t < t1; t++) {
        const int nxt = (cur == 2) ? 0 : cur + 1;
        // ---- prefetch tile t+1 into stage `nxt` (emb async, mask LDG->STS)
        if (t + 1 < t1) {
#pragma unroll
            for (int it = 0; it < 8; it++) {
                int f = it * THREADS + tid, r = f >> 4, c = f & 15;
                cp16(sb + SM_EMB + nxt * 32768 + r * 256 + ((c ^ (r & 7)) << 4),
                     embg + ((size_t)(t + 1) * 128 + r) * 256 + c * 16);
            }
        }
        asm volatile("cp.async.commit_group;" ::: "memory");
        if (t + 1 < t1) {
#pragma unroll
            for (int it = 0; it < 16; it++) {
                int row = it * 8 + w;
                int4 m = *reinterpret_cast<const int4*>(
                    &zs[(size_t)(b0 + row) * Z_DIM + (t + 1) * 128 + lane * 4]);
                uchar4 mb;
                mb.x = (m.x > 0) ? 0xFFu : 0u; mb.y = (m.y > 0) ? 0xFFu : 0u;
                mb.z = (m.z > 0) ? 0xFFu : 0u; mb.w = (m.w > 0) ? 0xFFu : 0u;
                *reinterpret_cast<uchar4*>(
                    smem + SM_MASK + nxt * MASK_BUF + row * MASK_P + lane * 4) = mb;
            }
        }

        asm volatile("cp.async.wait_group 1;" ::: "memory");
        __syncthreads();   // single barrier per tile: emb[t] + mask[t] ready everywhere

        const uint32_t eb = sb + SM_EMB + cur * 32768;
        const unsigned char* mask_s =
            reinterpret_cast<const unsigned char*>(smem + SM_MASK + cur * MASK_BUF);

        // S = ctx @ emb^T, fp16 accumulate (2x rate). C frag: s[f][0] = half2(row r,
        // z=8f+2tq..+1), s[f][1] = same for row r+8 -- already PV's A-operand layout.
        uint32_t s[16][2];
#pragma unroll
        for (int i = 0; i < 16; i++) { s[i][0] = 0u; s[i][1] = 0u; }
#pragma unroll
        for (int kk = 0; kk < 8; kk++) {
#pragma unroll
            for (int G = 0; G < 8; G++) {
                int rz = G * 16 + ((sub >> 1) << 3) + l7;
                int ch = 2 * kk + (sub & 1);
                uint32_t r0, r1, r2, r3;
                ldsm4(r0, r1, r2, r3, eb + rz * 256 + ((ch ^ (rz & 7)) << 4));
                mma16816h(s[2 * G], aCtx[kk], r0, r1);
                mma16816h(s[2 * G + 1], aCtx[kk], r2, r3);
            }
        }

        // packed-f16 softmax weights directly on fp16 score fragments
        const unsigned char* mrow0 = &mask_s[(wrow0 + g) * MASK_P];
        const unsigned char* mrow1 = mrow0 + 8 * MASK_P;
        uint32_t wlo[16], whi[16];
        uint32_t sa0 = 0, sa1 = 0;   // per-tile half2 accumulators
#pragma unroll
        for (int f = 0; f < 16; f++) {
            int zb = 8 * f + 2 * tq;
            uint32_t m0 = *reinterpret_cast<const unsigned short*>(&mrow0[zb]);
            uint32_t m1 = *reinterpret_cast<const unsigned short*>(&mrow1[zb]);
            cnt0 += __popc(m0);          // 8 per active feature
            cnt1 += __popc(m1);
            uint32_t w0 = ex2h2(s[f][0]) & prmt_sign(m0);
            uint32_t w1 = ex2h2(s[f][1]) & prmt_sign(m1);
            wlo[f] = w0; whi[f] = w1;
            sa0 = hadd2(sa0, w0);
            sa1 = hadd2(sa1, w1);
        }
        {   // fold per-tile half2 sums into fp32 running sums
            __half2 h0 = *reinterpret_cast<__half2*>(&sa0);
            __half2 h1 = *reinterpret_cast<__half2*>(&sa1);
            ssum0 += __low2float(h0) + __high2float(h0);
            ssum1 += __low2float(h1) + __high2float(h1);
        }

        // O += W @ emb  (A = packed W, B = trans ldmatrix of emb; fp32 accumulate)
#pragma unroll
        for (int kk = 0; kk < 8; kk++) {
            uint32_t aW[4] = { wlo[2 * kk], whi[2 * kk], wlo[2 * kk + 1], whi[2 * kk + 1] };
#pragma unroll
            for (int G = 0; G < 8; G++) {
                int rz = kk * 16 + ((sub & 1) << 3) + l7;
                int ch = 2 * G + (sub >> 1);
                uint32_t r0, r1, r2, r3;
                ldsm4t(r0, r1, r2, r3, eb + rz * 256 + ((ch ^ (rz & 7)) << 4));
                mma16816(o[2 * G], aW, r0, r1);
                mma16816(o[2 * G + 1], aW, r2, r3);
            }
        }
        cur = nxt;
    }

    // reduce ssums/cnts across the 4 lanes of each row-group
    ssum0 += __shfl_xor_sync(0xffffffffu, ssum0, 1);
    ssum0 += __shfl_xor_sync(0xffffffffu, ssum0, 2);
    ssum1 += __shfl_xor_sync(0xffffffffu, ssum1, 1);
    ssum1 += __shfl_xor_sync(0xffffffffu, ssum1, 2);
    cnt0 += __shfl_xor_sync(0xffffffffu, cnt0, 1);
    cnt0 += __shfl_xor_sync(0xffffffffu, cnt0, 2);
    cnt1 += __shfl_xor_sync(0xffffffffu, cnt1, 1);
    cnt1 += __shfl_xor_sync(0xffffffffu, cnt1, 2);
    int r0i = wrow0 + g;
    if (tq == 0) {
        int idx = chunk * B_DIM + b0 + r0i;
        g_pss[idx] = ssum0;  g_pcnt[idx] = cnt0 >> 3;
        g_pss[idx + 8] = ssum1; g_pcnt[idx + 8] = cnt1 >> 3;
    }

    // write O partials: thread's (f, c) element is at column d = 8*f + 2*tq + c
    float* p0 = g_pacc + ((size_t)chunk * B_DIM + b0 + r0i) * D_DIM;
    float* p1 = p0 + 8 * D_DIM;
    const int t2 = tq * 2;
#pragma unroll
    for (int f = 0; f < 16; f++) {
        *reinterpret_cast<float2*>(&p0[f * 8 + t2]) = make_float2(o[f][0], o[f][1]);
        *reinterpret_cast<float2*>(&p1[f * 8 + t2]) = make_float2(o[f][2], o[f][3]);
    }
}

__global__ void stage2_finalize(float* __restrict__ out)
{
    int i = blockIdx.x * blockDim.x + threadIdx.x;
    if (i >= B_DIM * D_DIM) return;
    int b = i >> 7;
    float accv = 0.f, ss = 0.f;
    int cc = 0;
#pragma unroll
    for (int c = 0; c < NCHUNK; c++) {
        accv += g_pacc[(size_t)c * (B_DIM * D_DIM) + i];
        ss   += g_pss[c * B_DIM + b];
        cc   += g_pcnt[c * B_DIM + b];
    }
    out[i] = (ss > 0.f) ? accv / (ss * (float)cc) : 0.f;
}

extern "C" void kernel_launch(void* const* d_in, const int* in_sizes, int n_in,
                              void* d_out, int out_size)
{
    const int*   zs  = (const int*)d_in[0];
    const float* ctx = (const float*)d_in[1];
    const float* emb = (const float*)d_in[2];
    float* out = (float*)d_out;

    conv_emb<<<2048, 256>>>(emb);
    cudaFuncSetAttribute(stage2_mma, cudaFuncAttributeMaxDynamicSharedMemorySize, SM_TOTAL);
    stage2_mma<<<dim3(8, NCHUNK), THREADS, SM_TOTAL>>>(zs, ctx);
    stage2_finalize<<<(B_DIM * D_DIM + 255) / 256, 256>>>(out);
}